// round 2
// baseline (speedup 1.0000x reference)
#include <cuda_runtime.h>
#include <cuda_bf16.h>
#include <math.h>

#define B_SZ 256
#define D_SZ 512

// ---------------- scratch (device globals; no allocation allowed) ----------
__device__ float g_q[B_SZ * D_SZ];
__device__ float g_k[B_SZ * D_SZ];
__device__ float g_v[B_SZ * D_SZ];
__device__ float g_o[B_SZ * D_SZ];
__device__ float g_it[B_SZ];
__device__ float g_ft[B_SZ];
__device__ float g_ht[B_SZ * D_SZ];

// ---------------- projection GEMM: Y[256,512] = X[256,512] @ W[512,512]^T --
// BM=64, BN=64, BK=16, 256 threads, each computes 4x4. Double-buffered smem.
// blockIdx.z selects {Wq,Wk,Wv,Wo}; z==3 fuses bias + sigmoid.
#define BM 64
#define BN 64
#define BK 16

__global__ __launch_bounds__(256) void proj_gemm(
    const float* __restrict__ X,
    const float* __restrict__ Wq, const float* __restrict__ Wk,
    const float* __restrict__ Wv, const float* __restrict__ Wo,
    const float* __restrict__ Wo_b)
{
    const float* W;
    float* Y;
    bool act = false;
    switch (blockIdx.z) {
        case 0: W = Wq; Y = g_q; break;
        case 1: W = Wk; Y = g_k; break;
        case 2: W = Wv; Y = g_v; break;
        default: W = Wo; Y = g_o; act = true; break;
    }

    __shared__ __align__(16) float As[2][BK][BM];
    __shared__ __align__(16) float Bs[2][BK][BN];

    const int tid  = threadIdx.x;
    const int m0   = blockIdx.y * BM;
    const int n0   = blockIdx.x * BN;
    const int lrow = tid >> 2;          // 0..63
    const int lcol = (tid & 3) * 4;     // 0,4,8,12

    const float* Aptr = X + (m0 + lrow) * D_SZ + lcol;
    const float* Bptr = W + (n0 + lrow) * D_SZ + lcol;

    // preload tile 0
    float4 a = *(const float4*)Aptr;
    float4 b = *(const float4*)Bptr;
    As[0][lcol + 0][lrow] = a.x; As[0][lcol + 1][lrow] = a.y;
    As[0][lcol + 2][lrow] = a.z; As[0][lcol + 3][lrow] = a.w;
    Bs[0][lcol + 0][lrow] = b.x; Bs[0][lcol + 1][lrow] = b.y;
    Bs[0][lcol + 2][lrow] = b.z; Bs[0][lcol + 3][lrow] = b.w;
    __syncthreads();

    const int tx = tid & 15;   // n subtile
    const int ty = tid >> 4;   // m subtile
    float acc[4][4] = {};

    const int KT = D_SZ / BK;  // 32
    int buf = 0;
    for (int t = 0; t < KT; ++t) {
        float4 na, nb;
        if (t + 1 < KT) {
            na = *(const float4*)(Aptr + (t + 1) * BK);
            nb = *(const float4*)(Bptr + (t + 1) * BK);
        }
        #pragma unroll
        for (int kk = 0; kk < BK; ++kk) {
            float4 av = *(const float4*)&As[buf][kk][ty * 4];
            float4 bv = *(const float4*)&Bs[buf][kk][tx * 4];
            acc[0][0] += av.x * bv.x; acc[0][1] += av.x * bv.y;
            acc[0][2] += av.x * bv.z; acc[0][3] += av.x * bv.w;
            acc[1][0] += av.y * bv.x; acc[1][1] += av.y * bv.y;
            acc[1][2] += av.y * bv.z; acc[1][3] += av.y * bv.w;
            acc[2][0] += av.z * bv.x; acc[2][1] += av.z * bv.y;
            acc[2][2] += av.z * bv.z; acc[2][3] += av.z * bv.w;
            acc[3][0] += av.w * bv.x; acc[3][1] += av.w * bv.y;
            acc[3][2] += av.w * bv.z; acc[3][3] += av.w * bv.w;
        }
        if (t + 1 < KT) {
            int nbuf = buf ^ 1;
            As[nbuf][lcol + 0][lrow] = na.x; As[nbuf][lcol + 1][lrow] = na.y;
            As[nbuf][lcol + 2][lrow] = na.z; As[nbuf][lcol + 3][lrow] = na.w;
            Bs[nbuf][lcol + 0][lrow] = nb.x; Bs[nbuf][lcol + 1][lrow] = nb.y;
            Bs[nbuf][lcol + 2][lrow] = nb.z; Bs[nbuf][lcol + 3][lrow] = nb.w;
        }
        __syncthreads();
        buf ^= 1;
    }

    const int row = m0 + ty * 4;
    const int col = n0 + tx * 4;
    #pragma unroll
    for (int i = 0; i < 4; ++i) {
        float4 r;
        r.x = acc[i][0]; r.y = acc[i][1]; r.z = acc[i][2]; r.w = acc[i][3];
        if (act) {
            r.x = 1.0f / (1.0f + __expf(-(r.x + Wo_b[col + 0])));
            r.y = 1.0f / (1.0f + __expf(-(r.y + Wo_b[col + 1])));
            r.z = 1.0f / (1.0f + __expf(-(r.z + Wo_b[col + 2])));
            r.w = 1.0f / (1.0f + __expf(-(r.w + Wo_b[col + 3])));
        }
        *(float4*)(Y + (size_t)(row + i) * D_SZ + col) = r;
    }
}

// ---------------- gate kernel: i_t, f_t (one warp per batch row) ------------
__global__ __launch_bounds__(256) void gates_kernel(
    const float* __restrict__ X,
    const float* __restrict__ wi_w, const float* __restrict__ wi_b,
    const float* __restrict__ wf_w, const float* __restrict__ wf_b)
{
    const int warp = threadIdx.x >> 5;
    const int lane = threadIdx.x & 31;
    const int b    = blockIdx.x * 8 + warp;

    const float4* x4  = (const float4*)(X + (size_t)b * D_SZ);
    const float4* wi4 = (const float4*)wi_w;
    const float4* wf4 = (const float4*)wf_w;

    float si = 0.f, sf = 0.f;
    #pragma unroll
    for (int r = 0; r < 4; ++r) {
        float4 x  = x4[lane + r * 32];
        float4 wi = wi4[lane + r * 32];
        float4 wf = wf4[lane + r * 32];
        si += x.x * wi.x + x.y * wi.y + x.z * wi.z + x.w * wi.w;
        sf += x.x * wf.x + x.y * wf.y + x.z * wf.z + x.w * wf.w;
    }
    #pragma unroll
    for (int o = 16; o; o >>= 1) {
        si += __shfl_down_sync(0xffffffffu, si, o);
        sf += __shfl_down_sync(0xffffffffu, sf, o);
    }
    if (lane == 0) {
        g_it[b] = fminf(expf(si + wi_b[0]), 50.0f);
        g_ft[b] = 1.0f / (1.0f + expf(-(sf + wf_b[0])));
    }
}

// ---------------- fused cell kernel: C_t + h_tilde partial ------------------
// grid(32, 256): 16 rows per block, 16 threads per row, float4 streaming.
__global__ __launch_bounds__(256) void cell_kernel(
    const float* __restrict__ Cprev, float* __restrict__ Ct)
{
    __shared__ __align__(16) float sk[D_SZ];
    __shared__ __align__(16) float sq[D_SZ];
    __shared__ float sv[16];

    const int b   = blockIdx.y;
    const int rb  = blockIdx.x;       // row block 0..31
    const int tid = threadIdx.x;      // 0..255

    if (tid < 128) {
        ((float4*)sk)[tid] = ((const float4*)(g_k + (size_t)b * D_SZ))[tid];
    } else {
        ((float4*)sq)[tid - 128] = ((const float4*)(g_q + (size_t)b * D_SZ))[tid - 128];
    }
    if (tid < 16) sv[tid] = g_v[(size_t)b * D_SZ + rb * 16 + tid];
    __syncthreads();

    const float f  = g_ft[b];
    const float it = g_it[b];
    const int r      = tid >> 4;       // local row 0..15
    const int lane16 = tid & 15;
    const int row    = rb * 16 + r;
    const float ivi  = it * sv[r];

    const float4* cp = (const float4*)(Cprev + (size_t)b * D_SZ * D_SZ + (size_t)row * D_SZ);
    float4*       ct = (float4*)(Ct   + (size_t)b * D_SZ * D_SZ + (size_t)row * D_SZ);
    const float4* k4 = (const float4*)sk;
    const float4* q4 = (const float4*)sq;

    float ht = 0.f;
    #pragma unroll
    for (int j = 0; j < 8; ++j) {
        const int idx = lane16 + j * 16;
        float4 c  = __ldcs(cp + idx);          // stream: no reuse
        float4 kv = k4[idx];
        float4 qv = q4[idx];
        float4 o;
        o.x = f * c.x + ivi * kv.x;
        o.y = f * c.y + ivi * kv.y;
        o.z = f * c.z + ivi * kv.z;
        o.w = f * c.w + ivi * kv.w;
        __stcs(ct + idx, o);                   // stream: no reuse
        ht += o.x * qv.x + o.y * qv.y + o.z * qv.z + o.w * qv.w;
    }
    #pragma unroll
    for (int off = 8; off; off >>= 1)
        ht += __shfl_down_sync(0xffffffffu, ht, off, 16);
    if (lane16 == 0) g_ht[(size_t)b * D_SZ + row] = ht;
}

// ---------------- epilogue: n_t, nq, h, LayerNorm ---------------------------
__device__ __forceinline__ float block_sum_256(float v, float* red)
{
    #pragma unroll
    for (int o = 16; o; o >>= 1) v += __shfl_down_sync(0xffffffffu, v, o);
    const int w = threadIdx.x >> 5;
    if ((threadIdx.x & 31) == 0) red[w] = v;
    __syncthreads();
    if (threadIdx.x < 8) {
        float s = red[threadIdx.x];
        #pragma unroll
        for (int o = 4; o; o >>= 1) s += __shfl_down_sync(0xffu, s, o);
        if (threadIdx.x == 0) red[0] = s;
    }
    __syncthreads();
    float r = red[0];
    __syncthreads();
    return r;
}

__global__ __launch_bounds__(256) void epilogue_kernel(
    const float* __restrict__ n_prev,
    const float* __restrict__ ln_g, const float* __restrict__ ln_b,
    float* __restrict__ out_h, float* __restrict__ out_n)
{
    __shared__ float red[8];
    const int b   = blockIdx.x;
    const int tid = threadIdx.x;
    const int e0  = tid;
    const int e1  = tid + 256;
    const size_t base = (size_t)b * D_SZ;

    const float f  = g_ft[b];
    const float it = g_it[b];

    const float k0 = g_k[base + e0], k1 = g_k[base + e1];
    const float q0 = g_q[base + e0], q1 = g_q[base + e1];
    const float nt0 = f * n_prev[base + e0] + it * k0;
    const float nt1 = f * n_prev[base + e1] + it * k1;
    out_n[base + e0] = nt0;
    out_n[base + e1] = nt1;

    const float nq = block_sum_256(nt0 * q0 + nt1 * q1, red);
    const float inv_den = 1.0f / fmaxf(fabsf(nq), 1.0f);

    const float h0 = g_o[base + e0] * g_ht[base + e0] * inv_den;
    const float h1 = g_o[base + e1] * g_ht[base + e1] * inv_den;

    const float mu = block_sum_256(h0 + h1, red) * (1.0f / (float)D_SZ);
    const float d0 = h0 - mu, d1 = h1 - mu;
    const float var = block_sum_256(d0 * d0 + d1 * d1, red) * (1.0f / (float)D_SZ);
    const float rstd = rsqrtf(var + 1e-5f);

    out_h[base + e0] = d0 * rstd * ln_g[e0] + ln_b[e0];
    out_h[base + e1] = d1 * rstd * ln_g[e1] + ln_b[e1];
}

// ---------------- launch ----------------------------------------------------
extern "C" void kernel_launch(void* const* d_in, const int* in_sizes, int n_in,
                              void* d_out, int out_size)
{
    const float* x_t    = (const float*)d_in[0];
    const float* C_prev = (const float*)d_in[1];
    const float* n_prev = (const float*)d_in[2];
    const float* Wq     = (const float*)d_in[3];
    const float* Wk     = (const float*)d_in[4];
    const float* Wv     = (const float*)d_in[5];
    const float* wi_w   = (const float*)d_in[6];
    const float* wi_b   = (const float*)d_in[7];
    const float* wf_w   = (const float*)d_in[8];
    const float* wf_b   = (const float*)d_in[9];
    const float* Wo     = (const float*)d_in[10];
    const float* Wo_b   = (const float*)d_in[11];
    const float* ln_g   = (const float*)d_in[12];
    const float* ln_b   = (const float*)d_in[13];

    float* out   = (float*)d_out;
    float* out_h = out;                                       // [256,512]
    float* out_C = out + (size_t)B_SZ * D_SZ;                 // [256,512,512]
    float* out_n = out + (size_t)B_SZ * D_SZ + (size_t)B_SZ * D_SZ * D_SZ; // [256,512]

    dim3 ggrid(D_SZ / BN, B_SZ / BM, 4);                      // (8,4,4)
    proj_gemm<<<ggrid, 256>>>(x_t, Wq, Wk, Wv, Wo, Wo_b);
    gates_kernel<<<B_SZ / 8, 256>>>(x_t, wi_w, wi_b, wf_w, wf_b);
    cell_kernel<<<dim3(D_SZ / 16, B_SZ), 256>>>(C_prev, out_C);
    epilogue_kernel<<<B_SZ, 256>>>(n_prev, ln_g, ln_b, out_h, out_n);
}